// round 2
// baseline (speedup 1.0000x reference)
#include <cuda_runtime.h>
#include <math.h>

// Problem constants (fixed by the dataset)
#define C_DIM   16
#define DK_DIM  8
#define NB_DIM  10
#define JDIM    16          // DIM_SH
#define NMAX    20000
#define EMAX    50000
#define AFEAT   4096        // 2 nets * 128 (jo) * 16 (t)

// Scratch (device globals — allocation-free)
__device__ float g_A[(size_t)NMAX * AFEAT];   // [n][net][jo][t], t fastest
__device__ float g_Wp[2 * 2048 * 16];         // [fpair][c][2]: {W[2fp][c], W[2fp+1][c]}
__device__ float g_q[NMAX * DK_DIM];
__device__ float g_expv[EMAX];
__device__ float g_v[EMAX * DK_DIM];
__device__ float g_z[NMAX];
// counting-sort scratch
__device__ int   g_count[NMAX];
__device__ int   g_rowstart[NMAX + 1];
__device__ int   g_cursor[NMAX];
__device__ int   g_esorted[EMAX];

// ---------------------------------------------------------------------------
// k0: permute Wk2/Wv2 ([16, 2048] col index (c*128 + j*8 + o)) into
//     Wp[fpair][c][2] where f = net*2048 + jo*16 + t  (A's f ordering).
__global__ void permute_w_kernel(const float* __restrict__ Wk2,
                                 const float* __restrict__ Wv2) {
    int idx = blockIdx.x * blockDim.x + threadIdx.x;   // 65536 threads
    if (idx >= 65536) return;
    int c   = idx & 15;
    int f   = idx >> 4;
    int t   = f & 15;
    int jo  = (f >> 4) & 127;
    int net = f >> 11;
    const float* W = net ? Wv2 : Wk2;
    int fp = f >> 1;
    g_Wp[(fp * 16 + c) * 2 + (f & 1)] = W[t * 2048 + c * 128 + jo];
}

// ---------------------------------------------------------------------------
// k1: q = x @ Wq   [N,16]@[16,8]
__global__ void q_kernel(const float* __restrict__ x,
                         const float* __restrict__ Wq, int N) {
    int i = blockIdx.x * blockDim.x + threadIdx.x;
    if (i >= N * DK_DIM) return;
    int n = i >> 3, o = i & 7;
    float s = 0.f;
#pragma unroll
    for (int c = 0; c < C_DIM; c++) s += x[n * C_DIM + c] * Wq[c * DK_DIM + o];
    g_q[i] = s;
}

// ---------------------------------------------------------------------------
// k2: A[n][f] = sum_c x[n,c] * W[f][c], packed f32x2 over f-pairs.
// Block: 32-node tile, 256 threads, thread owns f-pairs (fp0, fp0+256).
__global__ void __launch_bounds__(256) a_gemm_kernel(const float* __restrict__ x, int N) {
    __shared__ float2 xsd[C_DIM][32];    // duplicated {x,x} per (c, n)
    int tid = threadIdx.x;
    int n0  = blockIdx.x * 32;
    for (int i = tid; i < 512; i += 256) {
        int n = i >> 4, c = i & 15;
        int g = n0 + n;
        float v = (g < N) ? x[g * C_DIM + c] : 0.f;
        xsd[c][n] = make_float2(v, v);
    }
    __syncthreads();

    int fp0 = blockIdx.y * 512 + tid;        // f-pair indices (of 2048)
    int fp1 = fp0 + 256;

    // load pre-paired weights: w[c] = {W[2fp][c], W[2fp+1][c]} as u64
    const unsigned long long* wpa = (const unsigned long long*)g_Wp;
    unsigned long long w0[16], w1[16];
#pragma unroll
    for (int c = 0; c < 16; c++) { w0[c] = wpa[fp0 * 16 + c]; w1[c] = wpa[fp1 * 16 + c]; }

    unsigned long long* Aout = (unsigned long long*)g_A;

    int nmax = N - n0; if (nmax > 32) nmax = 32;
    for (int n = 0; n < nmax; n += 2) {
        unsigned long long a00 = 0ull, a01 = 0ull, a10 = 0ull, a11 = 0ull;
        // zero-init as f32x2 {0,0}: bit pattern 0 is {0.f,0.f}
#pragma unroll
        for (int c = 0; c < 16; c++) {
            // LDS128: {x[n,c],x[n,c],x[n+1,c],x[n+1,c]} (broadcast, conflict-free)
            float4 xv = *(const float4*)&xsd[c][n];
            unsigned long long xa = __double_as_longlong(0.0), xb;
            asm("mov.b64 %0, {%1, %2};" : "=l"(xa) : "f"(xv.x), "f"(xv.y));
            asm("mov.b64 %0, {%1, %2};" : "=l"(xb) : "f"(xv.z), "f"(xv.w));
            asm("fma.rn.f32x2 %0, %1, %2, %0;" : "+l"(a00) : "l"(xa), "l"(w0[c]));
            asm("fma.rn.f32x2 %0, %1, %2, %0;" : "+l"(a01) : "l"(xa), "l"(w1[c]));
            asm("fma.rn.f32x2 %0, %1, %2, %0;" : "+l"(a10) : "l"(xb), "l"(w0[c]));
            asm("fma.rn.f32x2 %0, %1, %2, %0;" : "+l"(a11) : "l"(xb), "l"(w1[c]));
        }
        size_t r0 = (size_t)(n0 + n) * 2048;
        size_t r1 = r0 + 2048;
        Aout[r0 + fp0] = a00;
        Aout[r0 + fp1] = a01;
        if (n + 1 < nmax) {
            Aout[r1 + fp0] = a10;
            Aout[r1 + fp1] = a11;
        }
    }
}

// ---------------------------------------------------------------------------
// counting sort of edges by src: histogram -> scan -> scatter
__global__ void hist_kernel(const int* __restrict__ esrc, int E) {
    int e = blockIdx.x * blockDim.x + threadIdx.x;
    if (e < E) atomicAdd(&g_count[esrc[e]], 1);
}

__global__ void __launch_bounds__(1024) scan_kernel(int N) {
    __shared__ int ssum[1024];
    int t = threadIdx.x;
    int chunk = (N + 1023) / 1024;
    int b = t * chunk;
    int e = b + chunk; if (e > N) e = N;
    int s = 0;
    for (int i = b; i < e; i++) s += g_count[i];
    ssum[t] = s;
    __syncthreads();
    for (int off = 1; off < 1024; off <<= 1) {
        int v = 0;
        if (t >= off) v = ssum[t - off];
        __syncthreads();
        if (t >= off) ssum[t] += v;
        __syncthreads();
    }
    int run = (t == 0) ? 0 : ssum[t - 1];
    for (int i = b; i < e; i++) {
        g_rowstart[i] = run;
        g_cursor[i]   = run;
        run += g_count[i];
    }
    if (t == 1023) g_rowstart[N] = run;
}

__global__ void sortscatter_kernel(const int* __restrict__ esrc, int E) {
    int e = blockIdx.x * blockDim.x + threadIdx.x;
    if (e >= E) return;
    int p = atomicAdd(&g_cursor[esrc[e]], 1);
    g_esorted[p] = e;
}

// ---------------------------------------------------------------------------
// k3: edge pass — one warp per SRC NODE, looping its CSR edges.
// A row streams from DRAM on the first edge, hits L1 on the rest.
__global__ void __launch_bounds__(256) edge_pass1_kernel(
    const float* __restrict__ pos,
    const float* __restrict__ Wk1, const float* __restrict__ Wv1,
    const int* __restrict__ edst, int N) {

    __shared__ float hsm[8][32];   // [warp][net*16 + t]
    __shared__ float shsm[8][16];  // [warp][j]

    int warp = threadIdx.x >> 5;
    int lane = threadIdx.x & 31;
    int n = blockIdx.x * 8 + warp;
    if (n >= N) return;            // warp-uniform

    int start = g_rowstart[n], end = g_rowstart[n + 1];
    if (start == end) return;

    float psx = pos[n * 3 + 0], psy = pos[n * 3 + 1], psz = pos[n * 3 + 2];
    const float* Abase = g_A + (size_t)n * AFEAT;
    int Lj = lane >> 3;
    int o_l = lane & 7;

    for (int i = start; i < end; i++) {
        int e = g_esorted[i];
        int dst = edst[e];

        float vx = psx - pos[dst * 3 + 0];
        float vy = psy - pos[dst * 3 + 1];
        float vz = psz - pos[dst * 3 + 2];
        float r2  = vx * vx + vy * vy + vz * vz;
        float rsh = sqrtf(r2);
        float inv = 1.f / fmaxf(rsh, 1e-9f);
        float ux = vx * inv, uy = vy * inv, uz = vz * inv;
        float r = sqrtf(r2 + 1e-18f);

        // spherical harmonics l=0..3 (component normalization)
        if (lane == 0) {
            float xx = ux * ux, yy = uy * uy, zz = uz * uz;
            float* S = shsm[warp];
            S[0]  = 1.f;
            S[1]  = 1.7320508f * ux;
            S[2]  = 1.7320508f * uy;
            S[3]  = 1.7320508f * uz;
            S[4]  = 3.8729833f * ux * uy;
            S[5]  = 3.8729833f * uy * uz;
            S[6]  = 1.1180340f * (3.f * zz - 1.f);
            S[7]  = 3.8729833f * ux * uz;
            S[8]  = 1.9364917f * (xx - yy);
            S[9]  = 2.0916501f * uy * (3.f * xx - yy);
            S[10] = 10.2469508f * ux * uy * uz;
            S[11] = 1.6201852f * uy * (5.f * zz - 1.f);
            S[12] = 1.3228757f * uz * (5.f * zz - 3.f);
            S[13] = 1.6201852f * ux * (5.f * zz - 1.f);
            S[14] = 5.1234754f * uz * (xx - yy);
            S[15] = 2.0916501f * ux * (xx - 3.f * yy);
        }

        // radial embedding + fcnet hidden: lanes 0..15 -> h_k[t], 16..31 -> h_v[t]
        {
            const float step = 3.5f / 11.f;
            const float EMB_K = 1.14136f * 7.3890561f * 3.16227766f;
            float rs = r / step;
            float emb[NB_DIM];
#pragma unroll
            for (int b = 0; b < NB_DIM; b++) {
                float u = rs - (float)(b + 1);
                float y = 0.f;
                if (fabsf(u) < 1.f) y = expf(-1.f / (1.f - u * u));
                emb[b] = EMB_K * y;
            }
            int net = lane >> 4, t = lane & 15;
            const float* W1 = net ? Wv1 : Wk1;
            float d = 0.f;
#pragma unroll
            for (int b = 0; b < NB_DIM; b++) d += emb[b] * W1[b * 16 + t];
            d *= 0.316227766f;
            hsm[warp][lane] = d / (1.f + expf(-d));   // silu
        }
        __syncwarp();

        float q_o = g_q[dst * DK_DIM + o_l];
        float results[2];

#pragma unroll
        for (int net = 0; net < 2; net++) {
            const float* Ab = Abase + net * 2048;
            const float* hh = hsm[warp] + net * 16;
            float kp = 0.f;
#pragma unroll
            for (int jj = 0; jj < 4; jj++) {
                int jo = lane + 32 * jj;        // j = Lj + 4*jj, o = lane&7
                const float4* ap = (const float4*)(Ab + jo * 16);
                float p = 0.f;
#pragma unroll
                for (int tt = 0; tt < 4; tt++) {
                    float4 a = ap[tt];
                    p += a.x * hh[4 * tt + 0] + a.y * hh[4 * tt + 1]
                       + a.z * hh[4 * tt + 2] + a.w * hh[4 * tt + 3];
                }
                kp += p * shsm[warp][Lj + 4 * jj];
            }
            kp += __shfl_xor_sync(0xffffffffu, kp, 8);
            kp += __shfl_xor_sync(0xffffffffu, kp, 16);
            results[net] = kp * (1.f / 64.f);   // /sqrt(16) fcnet, /sqrt(256) norm
        }

        if (lane < 8) g_v[e * DK_DIM + lane] = results[1];

        float prod = results[0] * q_o;
        prod += __shfl_xor_sync(0xffffffffu, prod, 1);
        prod += __shfl_xor_sync(0xffffffffu, prod, 2);
        prod += __shfl_xor_sync(0xffffffffu, prod, 4);

        if (lane == 0) {
            float logit = prod * 0.35355339f;   // / sqrt(8)
            float tcut = 10.f * (1.f - r * (1.f / 3.5f));
            float cut = (tcut > 0.f) ? expf(-1.f / tcut) : 0.f;
            float ev = cut * expf(logit);
            g_expv[e] = ev;
            atomicAdd(&g_z[dst], ev);
        }
        __syncwarp();
    }
}

// ---------------------------------------------------------------------------
// k4: scatter out[dst] += sqrt(relu(alpha)) * v
__global__ void scatter_kernel(const int* __restrict__ edst,
                               float* __restrict__ out, int E) {
    int i = blockIdx.x * blockDim.x + threadIdx.x;
    if (i >= E * DK_DIM) return;
    int e = i >> 3;
    int dst = edst[e];
    float z = g_z[dst];
    if (z == 0.f) z = 1.f;
    float a = g_expv[e] / z;
    float w = sqrtf(a);
    atomicAdd(&out[dst * DK_DIM + (i & 7)], w * g_v[i]);
}

// ---------------------------------------------------------------------------
extern "C" void kernel_launch(void* const* d_in, const int* in_sizes, int n_in,
                              void* d_out, int out_size) {
    const float* pos = (const float*)d_in[0];
    const float* x   = (const float*)d_in[1];
    const float* Wq  = (const float*)d_in[2];
    const float* Wk1 = (const float*)d_in[3];
    const float* Wk2 = (const float*)d_in[4];
    const float* Wv1 = (const float*)d_in[5];
    const float* Wv2 = (const float*)d_in[6];
    const int* esrc  = (const int*)d_in[7];
    const int* edst  = (const int*)d_in[8];

    int N = in_sizes[1] / C_DIM;
    int E = in_sizes[7];
    float* out = (float*)d_out;

    void* zptr = nullptr;  cudaGetSymbolAddress(&zptr, g_z);
    void* cptr = nullptr;  cudaGetSymbolAddress(&cptr, g_count);
    cudaMemsetAsync(zptr, 0, (size_t)N * sizeof(float));
    cudaMemsetAsync(cptr, 0, (size_t)N * sizeof(int));
    cudaMemsetAsync(out, 0, (size_t)out_size * sizeof(float));

    permute_w_kernel<<<256, 256>>>(Wk2, Wv2);
    q_kernel<<<(N * DK_DIM + 255) / 256, 256>>>(x, Wq, N);

    // counting sort edges by src
    hist_kernel<<<(E + 255) / 256, 256>>>(esrc, E);
    scan_kernel<<<1, 1024>>>(N);
    sortscatter_kernel<<<(E + 255) / 256, 256>>>(esrc, E);

    dim3 ga((N + 31) / 32, 4);
    a_gemm_kernel<<<ga, 256>>>(x, N);

    edge_pass1_kernel<<<(N + 7) / 8, 256>>>(pos, Wk1, Wv1, edst, N);
    scatter_kernel<<<(E * DK_DIM + 255) / 256, 256>>>(edst, out, E);
}

// round 3
// speedup vs baseline: 1.0428x; 1.0428x over previous
#include <cuda_runtime.h>
#include <math.h>

#define C_DIM   16
#define DK_DIM  8
#define NB_DIM  10
#define NMAX    20000
#define EMAX    50000
#define AFEAT   4096        // 2 nets * 128 (jo) * 16 (t)

__device__ float g_A[(size_t)NMAX * AFEAT];   // [n][net][jo][t], t fastest
__device__ float g_Wp[2 * 2048 * 16];         // [fpair][c][2]
__device__ float g_q[NMAX * DK_DIM];
__device__ float g_expv[EMAX];
__device__ float g_v[EMAX * DK_DIM];
__device__ float g_z[NMAX];
__device__ int   g_count[NMAX];
__device__ int   g_rowstart[NMAX];
__device__ int   g_cursor[NMAX];
__device__ int   g_esorted[EMAX];
__device__ int   g_sdst[EMAX];
__device__ int   g_total;

// ---------------------------------------------------------------------------
// k0: permute Wk2/Wv2 into paired layout Wp[fpair][c][2], f = net*2048+jo*16+t
__global__ void permute_w_kernel(const float* __restrict__ Wk2,
                                 const float* __restrict__ Wv2) {
    int idx = blockIdx.x * blockDim.x + threadIdx.x;
    if (idx >= 65536) return;
    int c   = idx & 15;
    int f   = idx >> 4;
    int t   = f & 15;
    int jo  = (f >> 4) & 127;
    int net = f >> 11;
    const float* W = net ? Wv2 : Wk2;
    int fp = f >> 1;
    g_Wp[(fp * 16 + c) * 2 + (f & 1)] = W[t * 2048 + c * 128 + jo];
}

// ---------------------------------------------------------------------------
__global__ void q_kernel(const float* __restrict__ x,
                         const float* __restrict__ Wq, int N) {
    int i = blockIdx.x * blockDim.x + threadIdx.x;
    if (i >= N * DK_DIM) return;
    int n = i >> 3, o = i & 7;
    float s = 0.f;
#pragma unroll
    for (int c = 0; c < C_DIM; c++) s += x[n * C_DIM + c] * Wq[c * DK_DIM + o];
    g_q[i] = s;
}

// ---------------------------------------------------------------------------
// k2: A[n][f] = sum_c x[n,c] * W[f][c], packed fma.rn.f32x2 over f-pairs.
__global__ void __launch_bounds__(256) a_gemm_kernel(const float* __restrict__ x, int N) {
    __shared__ __align__(16) float2 xsd[C_DIM][32];   // {v,v} per (c,n)
    int tid = threadIdx.x;
    int n0  = blockIdx.x * 32;
    for (int i = tid; i < 512; i += 256) {
        int n = i >> 4, c = i & 15;
        int g = n0 + n;
        float v = (g < N) ? x[g * C_DIM + c] : 0.f;
        xsd[c][n] = make_float2(v, v);
    }
    __syncthreads();

    int fp0 = blockIdx.y * 512 + tid;        // of 2048 f-pairs
    int fp1 = fp0 + 256;

    const unsigned long long* wpa = (const unsigned long long*)g_Wp;
    unsigned long long w0[16], w1[16];
#pragma unroll
    for (int c = 0; c < 16; c++) { w0[c] = wpa[fp0 * 16 + c]; w1[c] = wpa[fp1 * 16 + c]; }

    unsigned long long* Aout = (unsigned long long*)g_A;

    int nmax = N - n0; if (nmax > 32) nmax = 32;
    for (int n = 0; n < nmax; n += 2) {
        unsigned long long a00 = 0ull, a01 = 0ull, a10 = 0ull, a11 = 0ull;
#pragma unroll
        for (int c = 0; c < 16; c++) {
            ulonglong2 xv = *(const ulonglong2*)&xsd[c][n];  // LDS128: {xn,xn},{xn1,xn1}
            asm("fma.rn.f32x2 %0, %1, %2, %0;" : "+l"(a00) : "l"(xv.x), "l"(w0[c]));
            asm("fma.rn.f32x2 %0, %1, %2, %0;" : "+l"(a01) : "l"(xv.x), "l"(w1[c]));
            asm("fma.rn.f32x2 %0, %1, %2, %0;" : "+l"(a10) : "l"(xv.y), "l"(w0[c]));
            asm("fma.rn.f32x2 %0, %1, %2, %0;" : "+l"(a11) : "l"(xv.y), "l"(w1[c]));
        }
        size_t r0 = (size_t)(n0 + n) * 2048;
        Aout[r0 + fp0] = a00;
        Aout[r0 + fp1] = a01;
        if (n + 1 < nmax) {
            Aout[r0 + 2048 + fp0] = a10;
            Aout[r0 + 2048 + fp1] = a11;
        }
    }
}

// ---------------------------------------------------------------------------
// grouping by src: histogram -> atomic offset assign -> scatter
__global__ void hist_kernel(const int* __restrict__ esrc, int E) {
    int e = blockIdx.x * blockDim.x + threadIdx.x;
    if (e < E) atomicAdd(&g_count[esrc[e]], 1);
}

__global__ void assign_kernel(int N) {
    int n = blockIdx.x * blockDim.x + threadIdx.x;
    if (n >= N) return;
    int c = g_count[n];
    if (c > 0) {
        int s = atomicAdd(&g_total, c);
        g_rowstart[n] = s;
        g_cursor[n]   = s;
    }
}

__global__ void sortscatter_kernel(const int* __restrict__ esrc,
                                   const int* __restrict__ edst, int E) {
    int e = blockIdx.x * blockDim.x + threadIdx.x;
    if (e >= E) return;
    int p = atomicAdd(&g_cursor[esrc[e]], 1);
    g_esorted[p] = e;
    g_sdst[p]   = edst[e];
}

// ---------------------------------------------------------------------------
// k3: edge pass — one warp per src node, edges processed in groups of 4.
// A chunk is re-read within ~one jj-loop -> guaranteed L1 hits for ee>0.
__global__ void __launch_bounds__(256) edge_pass_kernel(
    const float* __restrict__ pos,
    const float* __restrict__ Wk1, const float* __restrict__ Wv1, int N) {

    __shared__ float hsm[8][4][32];   // [warp][ee][net*16+t]
    __shared__ float shs[8][4][16];   // [warp][ee][j]

    int warp = threadIdx.x >> 5;
    int lane = threadIdx.x & 31;
    int n = blockIdx.x * 8 + warp;
    if (n >= N) return;

    int d = g_count[n];
    if (d == 0) return;
    int base = g_rowstart[n];

    float psx = pos[n * 3 + 0], psy = pos[n * 3 + 1], psz = pos[n * 3 + 2];
    const float* Abase = g_A + (size_t)n * AFEAT;
    int Lj = lane >> 3;
    int o_l = lane & 7;

    for (int g0 = 0; g0 < d; g0 += 4) {
        int ng = d - g0; if (ng > 4) ng = 4;
        int eid[4], dstv[4];
        float rv[4];

#pragma unroll
        for (int ee = 0; ee < 4; ee++) {
            if (ee < ng) {
                int e   = g_esorted[base + g0 + ee];
                int dst = g_sdst[base + g0 + ee];
                eid[ee] = e; dstv[ee] = dst;

                float vx = psx - pos[dst * 3 + 0];
                float vy = psy - pos[dst * 3 + 1];
                float vz = psz - pos[dst * 3 + 2];
                float r2  = vx * vx + vy * vy + vz * vz;
                float rsh = sqrtf(r2);
                float inv = 1.f / fmaxf(rsh, 1e-9f);
                float ux = vx * inv, uy = vy * inv, uz = vz * inv;
                float r = sqrtf(r2 + 1e-18f);
                rv[ee] = r;

                if (lane == 0) {
                    float xx = ux * ux, yy = uy * uy, zz = uz * uz;
                    float* S = shs[warp][ee];
                    S[0]  = 1.f;
                    S[1]  = 1.7320508f * ux;
                    S[2]  = 1.7320508f * uy;
                    S[3]  = 1.7320508f * uz;
                    S[4]  = 3.8729833f * ux * uy;
                    S[5]  = 3.8729833f * uy * uz;
                    S[6]  = 1.1180340f * (3.f * zz - 1.f);
                    S[7]  = 3.8729833f * ux * uz;
                    S[8]  = 1.9364917f * (xx - yy);
                    S[9]  = 2.0916501f * uy * (3.f * xx - yy);
                    S[10] = 10.2469508f * ux * uy * uz;
                    S[11] = 1.6201852f * uy * (5.f * zz - 1.f);
                    S[12] = 1.3228757f * uz * (5.f * zz - 3.f);
                    S[13] = 1.6201852f * ux * (5.f * zz - 1.f);
                    S[14] = 5.1234754f * uz * (xx - yy);
                    S[15] = 2.0916501f * ux * (xx - 3.f * yy);
                }
                // radial emb + fcnet hidden: lanes 0..15 h_k, 16..31 h_v
                const float step = 3.5f / 11.f;
                const float EMB_K = 1.14136f * 7.3890561f * 3.16227766f;
                float rs = r / step;
                float emb[NB_DIM];
#pragma unroll
                for (int b = 0; b < NB_DIM; b++) {
                    float u = rs - (float)(b + 1);
                    float y = 0.f;
                    if (fabsf(u) < 1.f) y = expf(-1.f / (1.f - u * u));
                    emb[b] = EMB_K * y;
                }
                int net = lane >> 4, t = lane & 15;
                const float* W1 = net ? Wv1 : Wk1;
                float dd = 0.f;
#pragma unroll
                for (int b = 0; b < NB_DIM; b++) dd += emb[b] * W1[b * 16 + t];
                dd *= 0.316227766f;
                hsm[warp][ee][lane] = dd / (1.f + expf(-dd));
            }
        }
        __syncwarp();

        float p0[4] = {0.f, 0.f, 0.f, 0.f};
        float p1[4] = {0.f, 0.f, 0.f, 0.f};

#pragma unroll
        for (int net = 0; net < 2; net++) {
            const float* Ab = Abase + net * 2048;
#pragma unroll
            for (int ee = 0; ee < 4; ee++) {
                if (ee < ng) {
                    const float4* h4 = (const float4*)&hsm[warp][ee][net * 16];
                    float4 h0 = h4[0], h1 = h4[1], h2 = h4[2], h3 = h4[3];
                    float acc = 0.f;
#pragma unroll
                    for (int jj = 0; jj < 4; jj++) {
                        const float4* ap = (const float4*)(Ab + (lane + 32 * jj) * 16);
                        float4 a0 = ap[0], a1 = ap[1], a2 = ap[2], a3 = ap[3];
                        float t = a0.x*h0.x + a0.y*h0.y + a0.z*h0.z + a0.w*h0.w
                                + a1.x*h1.x + a1.y*h1.y + a1.z*h1.z + a1.w*h1.w
                                + a2.x*h2.x + a2.y*h2.y + a2.z*h2.z + a2.w*h2.w
                                + a3.x*h3.x + a3.y*h3.y + a3.z*h3.z + a3.w*h3.w;
                        acc += t * shs[warp][ee][Lj + 4 * jj];
                    }
                    if (net == 0) p0[ee] = acc; else p1[ee] = acc;
                }
            }
        }

#pragma unroll
        for (int ee = 0; ee < 4; ee++) {
            if (ee < ng) {
                float k = p0[ee];
                k += __shfl_xor_sync(0xffffffffu, k, 8);
                k += __shfl_xor_sync(0xffffffffu, k, 16);
                k *= (1.f / 64.f);
                float v = p1[ee];
                v += __shfl_xor_sync(0xffffffffu, v, 8);
                v += __shfl_xor_sync(0xffffffffu, v, 16);
                v *= (1.f / 64.f);
                if (lane < 8) g_v[eid[ee] * DK_DIM + lane] = v;

                float q_o = g_q[dstv[ee] * DK_DIM + o_l];
                float prod = k * q_o;
                prod += __shfl_xor_sync(0xffffffffu, prod, 1);
                prod += __shfl_xor_sync(0xffffffffu, prod, 2);
                prod += __shfl_xor_sync(0xffffffffu, prod, 4);

                if (lane == 0) {
                    float logit = prod * 0.35355339f;
                    float tcut = 10.f * (1.f - rv[ee] * (1.f / 3.5f));
                    float cut = (tcut > 0.f) ? expf(-1.f / tcut) : 0.f;
                    float ev = cut * expf(logit);
                    g_expv[eid[ee]] = ev;
                    atomicAdd(&g_z[dstv[ee]], ev);
                }
            }
        }
        __syncwarp();
    }
}

// ---------------------------------------------------------------------------
__global__ void scatter_kernel(const int* __restrict__ edst,
                               float* __restrict__ out, int E) {
    int i = blockIdx.x * blockDim.x + threadIdx.x;
    if (i >= E * DK_DIM) return;
    int e = i >> 3;
    int dst = edst[e];
    float z = g_z[dst];
    if (z == 0.f) z = 1.f;
    float a = g_expv[e] / z;
    float w = sqrtf(a);
    atomicAdd(&out[dst * DK_DIM + (i & 7)], w * g_v[i]);
}

// ---------------------------------------------------------------------------
extern "C" void kernel_launch(void* const* d_in, const int* in_sizes, int n_in,
                              void* d_out, int out_size) {
    const float* pos = (const float*)d_in[0];
    const float* x   = (const float*)d_in[1];
    const float* Wq  = (const float*)d_in[2];
    const float* Wk1 = (const float*)d_in[3];
    const float* Wk2 = (const float*)d_in[4];
    const float* Wv1 = (const float*)d_in[5];
    const float* Wv2 = (const float*)d_in[6];
    const int* esrc  = (const int*)d_in[7];
    const int* edst  = (const int*)d_in[8];

    int N = in_sizes[1] / C_DIM;
    int E = in_sizes[7];
    float* out = (float*)d_out;

    void* zptr = nullptr;  cudaGetSymbolAddress(&zptr, g_z);
    void* cptr = nullptr;  cudaGetSymbolAddress(&cptr, g_count);
    void* tptr = nullptr;  cudaGetSymbolAddress(&tptr, g_total);
    cudaMemsetAsync(zptr, 0, (size_t)N * sizeof(float));
    cudaMemsetAsync(cptr, 0, (size_t)N * sizeof(int));
    cudaMemsetAsync(tptr, 0, sizeof(int));
    cudaMemsetAsync(out, 0, (size_t)out_size * sizeof(float));

    permute_w_kernel<<<256, 256>>>(Wk2, Wv2);
    q_kernel<<<(N * DK_DIM + 255) / 256, 256>>>(x, Wq, N);

    hist_kernel<<<(E + 255) / 256, 256>>>(esrc, E);
    assign_kernel<<<(N + 255) / 256, 256>>>(N);
    sortscatter_kernel<<<(E + 255) / 256, 256>>>(esrc, edst, E);

    dim3 ga((N + 31) / 32, 4);
    a_gemm_kernel<<<ga, 256>>>(x, N);

    edge_pass_kernel<<<(N + 7) / 8, 256>>>(pos, Wk1, Wv1, N);
    scatter_kernel<<<(E * DK_DIM + 255) / 256, 256>>>(edst, out, E);
}

// round 4
// speedup vs baseline: 1.3089x; 1.2551x over previous
#include <cuda_runtime.h>
#include <math.h>

// Problem constants (fixed by the dataset)
#define C_DIM   16
#define DK_DIM  8
#define NB_DIM  10
#define NMAX    20000
#define EMAX    50000
#define AFEAT   4096        // 2 nets * 128 (jo) * 16 (t)

// Scratch (device globals — allocation-free)
__device__ float g_A[(size_t)NMAX * AFEAT];   // [n][net][jo][t], t fastest
__device__ float g_Wp[2 * 2048 * 16];         // [f][c]
__device__ float g_q[NMAX * DK_DIM];
__device__ float g_expv[EMAX];
__device__ float g_v[EMAX * DK_DIM];
__device__ float g_z[NMAX];
// grouping-by-src scratch
__device__ int   g_count[NMAX];
__device__ int   g_cursor[NMAX];
__device__ int   g_esorted[EMAX];
__device__ int   g_blocktotal;

// ---------------------------------------------------------------------------
// k0: permute Wk2/Wv2 ([16, 2048] col (c*128 + j*8 + o)) into Wp[f][c],
//     f = net*2048 + jo*16 + t (matches A layout, coalesced).
__global__ void permute_w_kernel(const float* __restrict__ Wk2,
                                 const float* __restrict__ Wv2) {
    int idx = blockIdx.x * blockDim.x + threadIdx.x;
    if (idx >= 65536) return;
    int c   = idx & 15;
    int f   = idx >> 4;
    int t   = f & 15;
    int jo  = (f >> 4) & 127;
    int net = f >> 11;
    const float* W = net ? Wv2 : Wk2;
    g_Wp[f * 16 + c] = W[t * 2048 + c * 128 + jo];
}

// ---------------------------------------------------------------------------
// k1: q = x @ Wq
__global__ void q_kernel(const float* __restrict__ x,
                         const float* __restrict__ Wq, int N) {
    int i = blockIdx.x * blockDim.x + threadIdx.x;
    if (i >= N * DK_DIM) return;
    int n = i >> 3, o = i & 7;
    float s = 0.f;
#pragma unroll
    for (int c = 0; c < C_DIM; c++) s += x[n * C_DIM + c] * Wq[c * DK_DIM + o];
    g_q[i] = s;
}

// ---------------------------------------------------------------------------
// k2: A[n][f] = sum_c x[n,c] * Wp[f][c]  (identical to R1's known-good kernel)
__global__ void __launch_bounds__(256) a_gemm_kernel(const float* __restrict__ x, int N) {
    __shared__ float xs[32][16];
    int tid = threadIdx.x;
    int n0  = blockIdx.x * 32;
    for (int i = tid; i < 512; i += 256) {
        int n = i >> 4, c = i & 15;
        int g = n0 + n;
        xs[n][c] = (g < N) ? x[g * C_DIM + c] : 0.f;
    }
    __syncthreads();

    int f = blockIdx.y * 256 + tid;
    const float4* wr = (const float4*)&g_Wp[f * 16];
    float4 w0 = wr[0], w1 = wr[1], w2 = wr[2], w3 = wr[3];

    int nmax = N - n0; if (nmax > 32) nmax = 32;
    for (int n = 0; n < nmax; n++) {
        const float* xr = xs[n];
        float s = w0.x * xr[0]  + w0.y * xr[1]  + w0.z * xr[2]  + w0.w * xr[3]
                + w1.x * xr[4]  + w1.y * xr[5]  + w1.z * xr[6]  + w1.w * xr[7]
                + w2.x * xr[8]  + w2.y * xr[9]  + w2.z * xr[10] + w2.w * xr[11]
                + w3.x * xr[12] + w3.y * xr[13] + w3.z * xr[14] + w3.w * xr[15];
        g_A[(size_t)(n0 + n) * AFEAT + f] = s;
    }
}

// ---------------------------------------------------------------------------
// grouping by src: histogram -> block-aggregated offset assign -> scatter.
__global__ void hist_kernel(const int* __restrict__ esrc, int E) {
    int e = blockIdx.x * blockDim.x + threadIdx.x;
    if (e < E) atomicAdd(&g_count[esrc[e]], 1);
}

// One atomic per BLOCK (not per node): intra-block exclusive scan in smem.
__global__ void __launch_bounds__(256) assign_kernel(int N) {
    __shared__ int s[256];
    __shared__ int base;
    int t = threadIdx.x;
    int n = blockIdx.x * 256 + t;
    int c = (n < N) ? g_count[n] : 0;
    s[t] = c;
    __syncthreads();
    // Hillis-Steele inclusive scan
#pragma unroll
    for (int off = 1; off < 256; off <<= 1) {
        int v = (t >= off) ? s[t - off] : 0;
        __syncthreads();
        s[t] += v;
        __syncthreads();
    }
    if (t == 255) base = atomicAdd(&g_blocktotal, s[255]);
    __syncthreads();
    if (n < N) g_cursor[n] = base + s[t] - c;   // exclusive start
}

__global__ void sortscatter_kernel(const int* __restrict__ esrc, int E) {
    int e = blockIdx.x * blockDim.x + threadIdx.x;
    if (e >= E) return;
    int p = atomicAdd(&g_cursor[esrc[e]], 1);
    g_esorted[p] = e;
}

// ---------------------------------------------------------------------------
// k3: edge pass — one warp per edge, edges visited in src-sorted order so
// adjacent warps hit the same A row (L1/L2 reuse). Body identical to R1.
__global__ void __launch_bounds__(256) edge_pass1_kernel(
    const float* __restrict__ pos,
    const float* __restrict__ Wk1, const float* __restrict__ Wv1,
    const int* __restrict__ esrc, const int* __restrict__ edst, int E) {

    __shared__ float hsm[8][32];   // [warp][net*16 + t]
    __shared__ float shsm[8][16];  // [warp][j]

    int warp = threadIdx.x >> 5;
    int lane = threadIdx.x & 31;
    int slot = blockIdx.x * 8 + warp;
    if (slot >= E) return;         // warp-uniform
    int e = g_esorted[slot];

    int src = esrc[e], dst = edst[e];

    float vx = pos[src * 3 + 0] - pos[dst * 3 + 0];
    float vy = pos[src * 3 + 1] - pos[dst * 3 + 1];
    float vz = pos[src * 3 + 2] - pos[dst * 3 + 2];
    float r2  = vx * vx + vy * vy + vz * vz;
    float rsh = sqrtf(r2);
    float inv = 1.f / fmaxf(rsh, 1e-9f);
    float ux = vx * inv, uy = vy * inv, uz = vz * inv;
    float r = sqrtf(r2 + 1e-18f);

    // spherical harmonics l=0..3 (component normalization)
    float xx = ux * ux, yy = uy * uy, zz = uz * uz;
    if (lane == 0) {
        float* S = shsm[warp];
        S[0]  = 1.f;
        S[1]  = 1.7320508f * ux;
        S[2]  = 1.7320508f * uy;
        S[3]  = 1.7320508f * uz;
        S[4]  = 3.8729833f * ux * uy;
        S[5]  = 3.8729833f * uy * uz;
        S[6]  = 1.1180340f * (3.f * zz - 1.f);
        S[7]  = 3.8729833f * ux * uz;
        S[8]  = 1.9364917f * (xx - yy);
        S[9]  = 2.0916501f * uy * (3.f * xx - yy);
        S[10] = 10.2469508f * ux * uy * uz;
        S[11] = 1.6201852f * uy * (5.f * zz - 1.f);
        S[12] = 1.3228757f * uz * (5.f * zz - 3.f);
        S[13] = 1.6201852f * ux * (5.f * zz - 1.f);
        S[14] = 5.1234754f * uz * (xx - yy);
        S[15] = 2.0916501f * ux * (xx - 3.f * yy);
    }

    // radial embedding + fcnet hidden: lanes 0..15 -> h_k[t], 16..31 -> h_v[t]
    {
        const float step = 3.5f / 11.f;
        const float EMB_K = 1.14136f * 7.3890561f * 3.16227766f; // 1.14136*e^2*sqrt(10)
        float rs = r / step;
        float emb[NB_DIM];
#pragma unroll
        for (int b = 0; b < NB_DIM; b++) {
            float u = rs - (float)(b + 1);
            float y = 0.f;
            if (fabsf(u) < 1.f) y = expf(-1.f / (1.f - u * u));
            emb[b] = EMB_K * y;
        }
        int net = lane >> 4, t = lane & 15;
        const float* W1 = net ? Wv1 : Wk1;
        float d = 0.f;
#pragma unroll
        for (int b = 0; b < NB_DIM; b++) d += emb[b] * W1[b * 16 + t];
        d *= 0.316227766f;                 // / sqrt(10)
        hsm[warp][lane] = d / (1.f + expf(-d));   // silu
    }
    __syncwarp();

    const float* Abase = g_A + (size_t)src * AFEAT;
    float q_o = g_q[dst * DK_DIM + (lane & 7)];
    int Lj = lane >> 3;
    float results[2];

#pragma unroll
    for (int net = 0; net < 2; net++) {
        const float* Ab = Abase + net * 2048;
        const float* hh = hsm[warp] + net * 16;
        float kp = 0.f;
#pragma unroll
        for (int jj = 0; jj < 4; jj++) {
            int jo = lane + 32 * jj;        // j = Lj + 4*jj, o = lane&7
            const float4* ap = (const float4*)(Ab + jo * 16);
            float p = 0.f;
#pragma unroll
            for (int tt = 0; tt < 4; tt++) {
                float4 a = ap[tt];
                p += a.x * hh[4 * tt + 0] + a.y * hh[4 * tt + 1]
                   + a.z * hh[4 * tt + 2] + a.w * hh[4 * tt + 3];
            }
            kp += p * shsm[warp][Lj + 4 * jj];
        }
        kp += __shfl_xor_sync(0xffffffffu, kp, 8);
        kp += __shfl_xor_sync(0xffffffffu, kp, 16);
        results[net] = kp * (1.f / 64.f);   // /sqrt(16) fcnet, /sqrt(256) norm
    }

    if (lane < 8) g_v[e * DK_DIM + lane] = results[1];

    float prod = results[0] * q_o;
    prod += __shfl_xor_sync(0xffffffffu, prod, 1);
    prod += __shfl_xor_sync(0xffffffffu, prod, 2);
    prod += __shfl_xor_sync(0xffffffffu, prod, 4);

    if (lane == 0) {
        float logit = prod * 0.35355339f;   // / sqrt(8)
        float tcut = 10.f * (1.f - r * (1.f / 3.5f));
        float cut = (tcut > 0.f) ? expf(-1.f / tcut) : 0.f;
        float ev = cut * expf(logit);
        g_expv[e] = ev;
        atomicAdd(&g_z[dst], ev);
    }
}

// ---------------------------------------------------------------------------
// k4: scatter out[dst] += sqrt(relu(alpha)) * v
__global__ void scatter_kernel(const int* __restrict__ edst,
                               float* __restrict__ out, int E) {
    int i = blockIdx.x * blockDim.x + threadIdx.x;
    if (i >= E * DK_DIM) return;
    int e = i >> 3;
    int dst = edst[e];
    float z = g_z[dst];
    if (z == 0.f) z = 1.f;
    float a = g_expv[e] / z;
    float w = sqrtf(a);
    atomicAdd(&out[dst * DK_DIM + (i & 7)], w * g_v[i]);
}

// ---------------------------------------------------------------------------
extern "C" void kernel_launch(void* const* d_in, const int* in_sizes, int n_in,
                              void* d_out, int out_size) {
    const float* pos = (const float*)d_in[0];
    const float* x   = (const float*)d_in[1];
    const float* Wq  = (const float*)d_in[2];
    const float* Wk1 = (const float*)d_in[3];
    const float* Wk2 = (const float*)d_in[4];
    const float* Wv1 = (const float*)d_in[5];
    const float* Wv2 = (const float*)d_in[6];
    const int* esrc  = (const int*)d_in[7];
    const int* edst  = (const int*)d_in[8];

    int N = in_sizes[1] / C_DIM;
    int E = in_sizes[7];
    float* out = (float*)d_out;

    void* zptr = nullptr;  cudaGetSymbolAddress(&zptr, g_z);
    void* cptr = nullptr;  cudaGetSymbolAddress(&cptr, g_count);
    void* tptr = nullptr;  cudaGetSymbolAddress(&tptr, g_blocktotal);
    cudaMemsetAsync(zptr, 0, (size_t)N * sizeof(float));
    cudaMemsetAsync(cptr, 0, (size_t)N * sizeof(int));
    cudaMemsetAsync(tptr, 0, sizeof(int));
    cudaMemsetAsync(out, 0, (size_t)out_size * sizeof(float));

    permute_w_kernel<<<256, 256>>>(Wk2, Wv2);
    q_kernel<<<(N * DK_DIM + 255) / 256, 256>>>(x, Wq, N);

    // group edges by src (order within/between groups irrelevant)
    hist_kernel<<<(E + 255) / 256, 256>>>(esrc, E);
    assign_kernel<<<(N + 255) / 256, 256>>>(N);
    sortscatter_kernel<<<(E + 255) / 256, 256>>>(esrc, E);

    dim3 ga((N + 31) / 32, AFEAT / 256);
    a_gemm_kernel<<<ga, 256>>>(x, N);

    edge_pass1_kernel<<<(E + 7) / 8, 256>>>(pos, Wk1, Wv1, esrc, edst, E);
    scatter_kernel<<<(E * DK_DIM + 255) / 256, 256>>>(edst, out, E);
}

// round 5
// speedup vs baseline: 1.4606x; 1.1159x over previous
#include <cuda_runtime.h>
#include <math.h>

#define C_DIM   16
#define DK_DIM  8
#define NB_DIM  10
#define NMAX    20000
#define EMAX    50000
#define GMAX    40000       // >= sum ceil(d/4) <= E/4 + N = 32500
#define AFEAT   4096        // 2 nets * (16 t * 128 jo), T-MAJOR within net

// Scratch (device globals — allocation-free)
__device__ float g_A[(size_t)NMAX * AFEAT];   // [n][net][t][jo]
__device__ float g_Wp[2 * 2048 * 16];         // [f][c], f = net*2048 + t*128 + jo
__device__ float g_q[NMAX * DK_DIM];
__device__ float g_expv[EMAX];
__device__ float g_v[EMAX * DK_DIM];
__device__ float g_z[NMAX];
// grouping scratch
__device__ int   g_count[NMAX];
__device__ int   g_rowstart[NMAX];
__device__ int   g_cursor[NMAX];
__device__ int   g_gofs[NMAX];
__device__ int   g_esorted[EMAX];
__device__ int   g_ginfo[GMAX];               // (base<<3)|cnt
__device__ int   g_gsrc[GMAX];
__device__ int   g_counters[2];               // [0]=edge total, [1]=group total

// ---------------------------------------------------------------------------
// k: permute Wk2/Wv2 ([16,2048], col = c*128 + jo) into Wp[f][c],
//    f = net*2048 + t*128 + jo  (T-MAJOR: matches new A layout).
__global__ void permute_w_kernel(const float* __restrict__ Wk2,
                                 const float* __restrict__ Wv2) {
    int idx = blockIdx.x * blockDim.x + threadIdx.x;
    if (idx >= 65536) return;
    int c   = idx & 15;
    int f   = idx >> 4;
    int jo  = f & 127;
    int t   = (f >> 7) & 15;
    int net = f >> 11;
    const float* W = net ? Wv2 : Wk2;
    g_Wp[f * 16 + c] = W[t * 2048 + c * 128 + jo];
}

// ---------------------------------------------------------------------------
__global__ void q_kernel(const float* __restrict__ x,
                         const float* __restrict__ Wq, int N) {
    int i = blockIdx.x * blockDim.x + threadIdx.x;
    if (i >= N * DK_DIM) return;
    int n = i >> 3, o = i & 7;
    float s = 0.f;
#pragma unroll
    for (int c = 0; c < C_DIM; c++) s += x[n * C_DIM + c] * Wq[c * DK_DIM + o];
    g_q[i] = s;
}

// ---------------------------------------------------------------------------
// a_gemm: A[n][f] = sum_c x[n,c] * Wp[f][c]  (R1's known-good kernel)
__global__ void __launch_bounds__(256) a_gemm_kernel(const float* __restrict__ x, int N) {
    __shared__ float xs[32][16];
    int tid = threadIdx.x;
    int n0  = blockIdx.x * 32;
    for (int i = tid; i < 512; i += 256) {
        int n = i >> 4, c = i & 15;
        int g = n0 + n;
        xs[n][c] = (g < N) ? x[g * C_DIM + c] : 0.f;
    }
    __syncthreads();

    int f = blockIdx.y * 256 + tid;
    const float4* wr = (const float4*)&g_Wp[f * 16];
    float4 w0 = wr[0], w1 = wr[1], w2 = wr[2], w3 = wr[3];

    int nmax = N - n0; if (nmax > 32) nmax = 32;
    for (int n = 0; n < nmax; n++) {
        const float* xr = xs[n];
        float s = w0.x * xr[0]  + w0.y * xr[1]  + w0.z * xr[2]  + w0.w * xr[3]
                + w1.x * xr[4]  + w1.y * xr[5]  + w1.z * xr[6]  + w1.w * xr[7]
                + w2.x * xr[8]  + w2.y * xr[9]  + w2.z * xr[10] + w2.w * xr[11]
                + w3.x * xr[12] + w3.y * xr[13] + w3.z * xr[14] + w3.w * xr[15];
        g_A[(size_t)(n0 + n) * AFEAT + f] = s;
    }
}

// ---------------------------------------------------------------------------
__global__ void hist_kernel(const int* __restrict__ esrc, int E) {
    int e = blockIdx.x * blockDim.x + threadIdx.x;
    if (e < E) atomicAdd(&g_count[esrc[e]], 1);
}

// Block-aggregated offset assignment for BOTH edge slots and group slots.
__global__ void __launch_bounds__(256) assign_kernel(int N) {
    __shared__ int s[256];
    __shared__ int sg[256];
    __shared__ int baseE, baseG;
    int t = threadIdx.x;
    int n = blockIdx.x * 256 + t;
    int c  = (n < N) ? g_count[n] : 0;
    int gc = (c + 3) >> 2;                 // ceil(d/4) groups
    s[t] = c; sg[t] = gc;
    __syncthreads();
#pragma unroll
    for (int off = 1; off < 256; off <<= 1) {
        int v  = (t >= off) ? s[t - off]  : 0;
        int vg = (t >= off) ? sg[t - off] : 0;
        __syncthreads();
        s[t] += v; sg[t] += vg;
        __syncthreads();
    }
    if (t == 255) {
        baseE = atomicAdd(&g_counters[0], s[255]);
        baseG = atomicAdd(&g_counters[1], sg[255]);
    }
    __syncthreads();
    if (n < N) {
        int st = baseE + s[t] - c;
        g_rowstart[n] = st;
        g_cursor[n]   = st;
        g_gofs[n]     = baseG + sg[t] - gc;
    }
}

__global__ void sortscatter_kernel(const int* __restrict__ esrc, int E) {
    int e = blockIdx.x * blockDim.x + threadIdx.x;
    if (e >= E) return;
    int p = atomicAdd(&g_cursor[esrc[e]], 1);
    g_esorted[p] = e;
}

__global__ void groupwrite_kernel(int N) {
    int n = blockIdx.x * blockDim.x + threadIdx.x;
    if (n >= N) return;
    int d = g_count[n];
    if (d == 0) return;
    int base = g_rowstart[n];
    int go   = g_gofs[n];
    int ng   = (d + 3) >> 2;
    for (int i = 0; i < ng; i++) {
        int cnt = d - 4 * i; if (cnt > 4) cnt = 4;
        g_ginfo[go + i] = ((base + 4 * i) << 3) | cnt;
        g_gsrc[go + i]  = n;
    }
}

// ---------------------------------------------------------------------------
// edge pass: one 128-thread block per group (<=4 edges, same src).
// Block streams A[src] (16 KB, t-major) global->smem ONCE; each warp
// contracts its edge from smem (conflict-free lane-stride-1 over jo).
__global__ void __launch_bounds__(128) edge_pass_kernel(
    const float* __restrict__ pos,
    const float* __restrict__ Wk1, const float* __restrict__ Wv1,
    const int* __restrict__ edst) {

    __shared__ __align__(16) float sA[AFEAT];   // [net][t][jo]
    __shared__ float hsm[4][32];
    __shared__ float shs[4][16];

    if (blockIdx.x >= g_counters[1]) return;
    int info = g_ginfo[blockIdx.x];
    int src  = g_gsrc[blockIdx.x];
    int base = info >> 3;
    int cnt  = info & 7;

    int tid  = threadIdx.x;
    int warp = tid >> 5;
    int lane = tid & 31;

    // cooperative A row load: 4096 floats = 1024 float4, 8 per thread
    {
        const float4* Ar = (const float4*)(g_A + (size_t)src * AFEAT);
        float4* As = (float4*)sA;
#pragma unroll
        for (int i = 0; i < 8; i++) As[tid + 128 * i] = Ar[tid + 128 * i];
    }

    int e = -1, dst = 0;
    float r = 0.f;
    if (warp < cnt) {
        e   = g_esorted[base + warp];
        dst = edst[e];

        float vx = pos[src * 3 + 0] - pos[dst * 3 + 0];
        float vy = pos[src * 3 + 1] - pos[dst * 3 + 1];
        float vz = pos[src * 3 + 2] - pos[dst * 3 + 2];
        float r2  = vx * vx + vy * vy + vz * vz;
        float rsh = sqrtf(r2);
        float inv = 1.f / fmaxf(rsh, 1e-9f);
        float ux = vx * inv, uy = vy * inv, uz = vz * inv;
        r = sqrtf(r2 + 1e-18f);

        if (lane == 0) {
            float xx = ux * ux, yy = uy * uy, zz = uz * uz;
            float* S = shs[warp];
            S[0]  = 1.f;
            S[1]  = 1.7320508f * ux;
            S[2]  = 1.7320508f * uy;
            S[3]  = 1.7320508f * uz;
            S[4]  = 3.8729833f * ux * uy;
            S[5]  = 3.8729833f * uy * uz;
            S[6]  = 1.1180340f * (3.f * zz - 1.f);
            S[7]  = 3.8729833f * ux * uz;
            S[8]  = 1.9364917f * (xx - yy);
            S[9]  = 2.0916501f * uy * (3.f * xx - yy);
            S[10] = 10.2469508f * ux * uy * uz;
            S[11] = 1.6201852f * uy * (5.f * zz - 1.f);
            S[12] = 1.3228757f * uz * (5.f * zz - 3.f);
            S[13] = 1.6201852f * ux * (5.f * zz - 1.f);
            S[14] = 5.1234754f * uz * (xx - yy);
            S[15] = 2.0916501f * ux * (xx - 3.f * yy);
        }
        // radial emb + fcnet hidden: lanes 0..15 h_k[t], 16..31 h_v[t]
        {
            const float step = 3.5f / 11.f;
            const float EMB_K = 1.14136f * 7.3890561f * 3.16227766f;
            float rs = r / step;
            float emb[NB_DIM];
#pragma unroll
            for (int b = 0; b < NB_DIM; b++) {
                float u = rs - (float)(b + 1);
                float y = 0.f;
                if (fabsf(u) < 1.f) y = expf(-1.f / (1.f - u * u));
                emb[b] = EMB_K * y;
            }
            int net = lane >> 4, t = lane & 15;
            const float* W1 = net ? Wv1 : Wk1;
            float d = 0.f;
#pragma unroll
            for (int b = 0; b < NB_DIM; b++) d += emb[b] * W1[b * 16 + t];
            d *= 0.316227766f;
            hsm[warp][lane] = d / (1.f + expf(-d));
        }
    }
    __syncthreads();

    if (warp < cnt) {
        int o_l = lane & 7;
        float results[2];
#pragma unroll
        for (int net = 0; net < 2; net++) {
            const float* An = sA + net * 2048;
            float hr[16];
#pragma unroll
            for (int t = 0; t < 16; t++) hr[t] = hsm[warp][net * 16 + t];
            float kp = 0.f;
#pragma unroll
            for (int jj = 0; jj < 4; jj++) {
                const float* col = An + lane + 32 * jj;
                float p = 0.f;
#pragma unroll
                for (int t = 0; t < 16; t++) p += col[t * 128] * hr[t];
                kp += p * shs[warp][(lane >> 3) + 4 * jj];
            }
            kp += __shfl_xor_sync(0xffffffffu, kp, 8);
            kp += __shfl_xor_sync(0xffffffffu, kp, 16);
            results[net] = kp * (1.f / 64.f);
        }

        if (lane < 8) g_v[e * DK_DIM + lane] = results[1];

        float q_o = g_q[dst * DK_DIM + o_l];
        float prod = results[0] * q_o;
        prod += __shfl_xor_sync(0xffffffffu, prod, 1);
        prod += __shfl_xor_sync(0xffffffffu, prod, 2);
        prod += __shfl_xor_sync(0xffffffffu, prod, 4);

        if (lane == 0) {
            float logit = prod * 0.35355339f;
            float tcut = 10.f * (1.f - r * (1.f / 3.5f));
            float cut = (tcut > 0.f) ? expf(-1.f / tcut) : 0.f;
            float ev = cut * expf(logit);
            g_expv[e] = ev;
            atomicAdd(&g_z[dst], ev);
        }
    }
}

// ---------------------------------------------------------------------------
__global__ void scatter_kernel(const int* __restrict__ edst,
                               float* __restrict__ out, int E) {
    int i = blockIdx.x * blockDim.x + threadIdx.x;
    if (i >= E * DK_DIM) return;
    int e = i >> 3;
    int dst = edst[e];
    float z = g_z[dst];
    if (z == 0.f) z = 1.f;
    float a = g_expv[e] / z;
    float w = sqrtf(a);
    atomicAdd(&out[dst * DK_DIM + (i & 7)], w * g_v[i]);
}

// ---------------------------------------------------------------------------
extern "C" void kernel_launch(void* const* d_in, const int* in_sizes, int n_in,
                              void* d_out, int out_size) {
    const float* pos = (const float*)d_in[0];
    const float* x   = (const float*)d_in[1];
    const float* Wq  = (const float*)d_in[2];
    const float* Wk1 = (const float*)d_in[3];
    const float* Wk2 = (const float*)d_in[4];
    const float* Wv1 = (const float*)d_in[5];
    const float* Wv2 = (const float*)d_in[6];
    const int* esrc  = (const int*)d_in[7];
    const int* edst  = (const int*)d_in[8];

    int N = in_sizes[1] / C_DIM;
    int E = in_sizes[7];
    float* out = (float*)d_out;

    void* zptr = nullptr;   cudaGetSymbolAddress(&zptr, g_z);
    void* cptr = nullptr;   cudaGetSymbolAddress(&cptr, g_count);
    void* ctrp = nullptr;   cudaGetSymbolAddress(&ctrp, g_counters);
    cudaMemsetAsync(zptr, 0, (size_t)N * sizeof(float));
    cudaMemsetAsync(cptr, 0, (size_t)N * sizeof(int));
    cudaMemsetAsync(ctrp, 0, 2 * sizeof(int));
    cudaMemsetAsync(out, 0, (size_t)out_size * sizeof(float));

    // order chosen so a_gemm is the 4th kernel (the ncu-captured slot)
    permute_w_kernel<<<256, 256>>>(Wk2, Wv2);
    hist_kernel<<<(E + 255) / 256, 256>>>(esrc, E);
    assign_kernel<<<(N + 255) / 256, 256>>>(N);

    dim3 ga((N + 31) / 32, AFEAT / 256);
    a_gemm_kernel<<<ga, 256>>>(x, N);

    sortscatter_kernel<<<(E + 255) / 256, 256>>>(esrc, E);
    groupwrite_kernel<<<(N + 255) / 256, 256>>>(N);
    q_kernel<<<(N * DK_DIM + 255) / 256, 256>>>(x, Wq, N);

    int maxgroups = E / 4 + N;   // >= actual group count
    edge_pass_kernel<<<maxgroups, 128>>>(pos, Wk1, Wv1, edst);
    scatter_kernel<<<(E * DK_DIM + 255) / 256, 256>>>(edst, out, E);
}